// round 10
// baseline (speedup 1.0000x reference)
#include <cuda_runtime.h>
#include <cuda_fp16.h>
#include <math.h>
#include <stdint.h>

#define Bb   2
#define SS   4096
#define HH   512
#define NHH  8
#define HDD  64
#define MTOT (Bb*SS)

#define QPREMUL (0.125f * 1.44269504088896340736f)

__device__ __half g_Xh [(size_t)MTOT*HH];
__device__ __half g_Wqh[(size_t)HH*HH];
__device__ __half g_Wkh[(size_t)HH*HH];
__device__ __half g_Wvh[(size_t)HH*HH];
__device__ __half g_Woh[(size_t)HH*HH];
__device__ __half g_Q  [(size_t)Bb*NHH*SS*HDD];   // [b,h,s,d] * scale*log2e
__device__ __half g_K  [(size_t)Bb*NHH*SS*HDD];   // [b,h,s,d]
__device__ __half g_V  [(size_t)Bb*NHH*SS*HDD];   // [b,h,d,s]  (transposed)
__device__ __half g_ctxh[(size_t)Bb*SS*HH];       // [b,s,h]

__device__ __forceinline__ unsigned packh2(float a, float b) {
    __half2 h = __floats2half2_rn(a, b);
    return *(unsigned*)&h;
}
__device__ __forceinline__ uint32_t smem_u32(const void* p) {
    return (uint32_t)__cvta_generic_to_shared(p);
}
__device__ __forceinline__ void mma16(float d[4], const unsigned a[4],
                                      unsigned b0, unsigned b1) {
    asm volatile(
        "mma.sync.aligned.m16n8k16.row.col.f32.f16.f16.f32 "
        "{%0,%1,%2,%3}, {%4,%5,%6,%7}, {%8,%9}, {%0,%1,%2,%3};"
        : "+f"(d[0]), "+f"(d[1]), "+f"(d[2]), "+f"(d[3])
        : "r"(a[0]), "r"(a[1]), "r"(a[2]), "r"(a[3]), "r"(b0), "r"(b1));
}
#define LDSM4(r0, r1, r2, r3, addr) \
    asm volatile("ldmatrix.sync.aligned.m8n8.x4.shared.b16 {%0,%1,%2,%3}, [%4];" \
        : "=r"(r0), "=r"(r1), "=r"(r2), "=r"(r3) : "r"(addr))
// half2 = {lo = exp2(slo), hi = exp2(shi)}
#define EX2H2(dst, shi, slo) do { \
    unsigned _h; \
    asm("cvt.rn.f16x2.f32 %0, %1, %2;" : "=r"(_h) : "f"(shi), "f"(slo)); \
    asm("ex2.approx.f16x2 %0, %1;" : "=r"(dst) : "r"(_h)); \
} while (0)

#define CPASYNC16(dst_u32, src_ptr) \
    asm volatile("cp.async.ca.shared.global [%0], [%1], 16;" \
                 :: "r"(dst_u32), "l"(src_ptr) : "memory")
#define CPCOMMIT()  asm volatile("cp.async.commit_group;" ::: "memory")
#define CPWAIT2()   asm volatile("cp.async.wait_group 2;" ::: "memory")
#define CPWAIT0()   asm volatile("cp.async.wait_group 0;" ::: "memory")

__global__ void __launch_bounds__(256)
cvt_kernel(const float* __restrict__ x,
           const float* __restrict__ wq, const float* __restrict__ wk,
           const float* __restrict__ wv, const float* __restrict__ wo)
{
    int seg = blockIdx.y;
    const float* src; __half* dst; int n4;
    if      (seg == 0) { src = x;  dst = g_Xh;  n4 = (MTOT * HH) / 4; }
    else if (seg == 1) { src = wq; dst = g_Wqh; n4 = (HH * HH) / 4; }
    else if (seg == 2) { src = wk; dst = g_Wkh; n4 = (HH * HH) / 4; }
    else if (seg == 3) { src = wv; dst = g_Wvh; n4 = (HH * HH) / 4; }
    else               { src = wo; dst = g_Woh; n4 = (HH * HH) / 4; }
    int stride = gridDim.x * 256;
    for (int i = blockIdx.x * 256 + threadIdx.x; i < n4; i += stride) {
        float4 v = ((const float4*)src)[i];
        ((uint2*)dst)[i] = make_uint2(packh2(v.x, v.y), packh2(v.z, v.w));
    }
}

// ---------------------------------------------------------------------------
// half GEMM, cp.async double-buffered, ldmatrix fragment loads, 2 CTAs/SM.
// mode: 0 = [M,H] f32 out; 1 = g_Q half(v*premul); 2 = g_V transposed; 3 = g_K
// ---------------------------------------------------------------------------
#define GKS   20
#define GTILE (128 * GKS)

__device__ __forceinline__ void gemm128h(
    const __half* __restrict__ x, const __half* __restrict__ w,
    const float* __restrict__ bias, float* __restrict__ out,
    int bm0, int bn0, int mode, float premul)
{
    __shared__ unsigned Xs[2 * GTILE];
    __shared__ unsigned Ws[2 * GTILE];
    const uint32_t sbX = smem_u32(Xs), sbW = smem_u32(Ws);

    const int tid  = threadIdx.x;
    const int wrp  = tid >> 5;
    const int lane = tid & 31;
    const int g    = lane >> 2;
    const int t    = lane & 3;
    const int wm   = wrp >> 2;
    const int wn   = wrp & 3;

    const uint32_t lmo_b = (((uint32_t)(lane & 7)) * GKS + ((uint32_t)(lane >> 3)) * 4) * 4;
    const uint32_t lmo_a = ((((uint32_t)(lane >> 4)) * 8 + (lane & 7)) * GKS
                            + (((uint32_t)(lane >> 3)) & 1) * 4) * 4;

    auto issue_g = [&](int k0, int st) {
#pragma unroll
        for (int p = 0; p < 2; p++) {
            int idx = tid + p * 256;
            int row = idx >> 2;
            int cc  = idx & 3;
            CPASYNC16(sbX + (st * GTILE + row * GKS) * 4 + cc * 16,
                      x + (size_t)(bm0 + row) * HH + k0 + cc * 8);
            CPASYNC16(sbW + (st * GTILE + row * GKS) * 4 + cc * 16,
                      w + (size_t)(bn0 + row) * HH + k0 + cc * 8);
        }
    };

    float acc[4][4][4];
#pragma unroll
    for (int i = 0; i < 4; i++)
#pragma unroll
        for (int j = 0; j < 4; j++)
#pragma unroll
            for (int q = 0; q < 4; q++) acc[i][j][q] = 0.f;

    issue_g(0, 0);
    CPCOMMIT();

    for (int s = 0; s < 16; s++) {
        CPWAIT0();
        __syncthreads();
        if (s < 15) { issue_g((s + 1) * 32, (s + 1) & 1); CPCOMMIT(); }
        const uint32_t xb = sbX + (s & 1) * GTILE * 4;
        const uint32_t wb = sbW + (s & 1) * GTILE * 4;

        unsigned bw[4][4];
#pragma unroll
        for (int j = 0; j < 4; j++)
            LDSM4(bw[j][0], bw[j][1], bw[j][2], bw[j][3],
                  wb + (uint32_t)((wn * 32 + j * 8) * GKS) * 4 + lmo_b);

#pragma unroll
        for (int kc = 0; kc < 2; kc++) {
#pragma unroll
            for (int i = 0; i < 4; i++) {
                unsigned a[4];
                LDSM4(a[0], a[2], a[1], a[3],
                      xb + (uint32_t)((wm * 64 + i * 16) * GKS + kc * 8) * 4 + lmo_a);
#pragma unroll
                for (int j = 0; j < 4; j++)
                    mma16(acc[i][j], a, bw[j][2 * kc], bw[j][2 * kc + 1]);
            }
        }
    }

#pragma unroll
    for (int i = 0; i < 4; i++) {
        int m0 = bm0 + wm * 64 + i * 16 + g;
#pragma unroll
        for (int j = 0; j < 4; j++) {
            int n = bn0 + wn * 32 + j * 8 + 2 * t;
            float bi0 = bias[n], bi1 = bias[n + 1];
#pragma unroll
            for (int rr = 0; rr < 2; rr++) {
                int m = m0 + rr * 8;
                float v0 = acc[i][j][rr * 2 + 0] + bi0;
                float v1 = acc[i][j][rr * 2 + 1] + bi1;
                if (mode == 1 || mode == 3) {
                    int b_ = m >> 12, sq = m & (SS - 1);
                    int h  = n >> 6,  d = n & 63;
                    __half* dst = (mode == 1) ? g_Q : g_K;
                    __half* p = dst + (((size_t)b_ * NHH + h) * SS + sq) * HDD + d;
                    *(unsigned*)p = packh2(v0 * premul, v1 * premul);
                } else if (mode == 2) {
                    int b_ = m >> 12, sq = m & (SS - 1);
                    int h  = n >> 6,  d = n & 63;
                    __half* base = g_V + ((size_t)b_ * NHH + h) * (size_t)HDD * SS + sq;
                    base[(size_t)d * SS]       = __float2half_rn(v0);
                    base[(size_t)(d + 1) * SS] = __float2half_rn(v1);
                } else {
                    float* p = out + (size_t)m * HH + n;
                    p[0] = v0; p[1] = v1;
                }
            }
        }
    }
}

__global__ void __launch_bounds__(256, 2)
qkv_kernel(const float* __restrict__ bq, const float* __restrict__ bk,
           const float* __restrict__ bv)
{
    int z = blockIdx.z;
    const __half* W   = (z == 0) ? g_Wqh : (z == 1) ? g_Wkh : g_Wvh;
    const float* bias = (z == 0) ? bq : (z == 1) ? bk : bv;
    int   mode        = (z == 0) ? 1 : (z == 1) ? 3 : 2;
    float premul      = (z == 0) ? QPREMUL : 1.0f;
    gemm128h(g_Xh, W, bias, nullptr, blockIdx.y * 128, blockIdx.x * 128, mode, premul);
}

__global__ void __launch_bounds__(256, 2)
proj_kernel(const float* __restrict__ bo, float* __restrict__ out)
{
    gemm128h(g_ctxh, g_Woh, bo, out, blockIdx.y * 128, blockIdx.x * 128, 0, 1.0f);
}

// ---------------------------------------------------------------------------
// Flash attention: fp16 mma + ldmatrix + f16x2 exp2.
// 2-tile macro-iteration over a 6-stage cp.async ring: ONE barrier and ONE
// wait per 128 keys; 4 tiles in flight. Row-sum on the FMA pipe (HADD2 tree).
// ---------------------------------------------------------------------------
#define FSTR    36
#define ROWB    144
#define STAGEB  (64 * ROWB)                  // 9216 per K or V stage
#define NSTG    6
#define VOFFB   (NSTG * STAGEB)              // 55296
#define FLASH_SMEM (2 * NSTG * STAGEB)       // 110592 B
#define NT (SS / 64)

__global__ void __launch_bounds__(256, 2)
flash_kernel()
{
    extern __shared__ unsigned sm[];
    const uint32_t sb = smem_u32(sm);

    const int tid  = threadIdx.x;
    const int wrp  = tid >> 5;
    const int lane = tid & 31;
    const int g    = lane >> 2;
    const int t    = lane & 3;
    const int qt   = blockIdx.x;
    const int h    = blockIdx.y;
    const int b_   = blockIdx.z;

    const size_t hb = (size_t)(b_ * NHH + h);
    const __half* Qg = g_Q + hb * SS * HDD + (size_t)qt * 128 * HDD;
    const __half* Kg = g_K + hb * SS * HDD;
    const __half* Vt = g_V + hb * (size_t)HDD * SS;

    const uint32_t lmo = (((uint32_t)(lane & 7)) * FSTR + ((uint32_t)(lane >> 3)) * 4) * 4;

    auto issue_kv = [&](int kt) {
        int st = kt % NSTG;
#pragma unroll
        for (int p = 0; p < 2; p++) {
            int idx = tid + p * 256;
            int row = idx >> 3;
            int cc  = idx & 7;
            CPASYNC16(sb + st * STAGEB + row * ROWB + cc * 16,
                      Kg + (size_t)(kt * 64 + row) * HDD + cc * 8);
            CPASYNC16(sb + VOFFB + st * STAGEB + row * ROWB + cc * 16,
                      Vt + (size_t)row * SS + kt * 64 + cc * 8);
        }
    };

    issue_kv(0); CPCOMMIT();
    issue_kv(1); CPCOMMIT();
    issue_kv(2); CPCOMMIT();
    issue_kv(3); CPCOMMIT();

    // Q fragments straight from gmem
    const int r0 = wrp * 16 + g;
    unsigned aq[4][4];
#pragma unroll
    for (int kc = 0; kc < 4; kc++) {
        const __half* q0 = Qg + (size_t)r0 * HDD + kc * 16 + 2 * t;
        const __half* q1 = q0 + 8 * HDD;
        aq[kc][0] = *(const unsigned*)(q0);
        aq[kc][1] = *(const unsigned*)(q1);
        aq[kc][2] = *(const unsigned*)(q0 + 8);
        aq[kc][3] = *(const unsigned*)(q1 + 8);
    }

    float oacc[8][4];
#pragma unroll
    for (int n = 0; n < 8; n++)
#pragma unroll
        for (int q = 0; q < 4; q++) oacc[n][q] = 0.f;

    float l0 = 0.f, l1 = 0.f;
    float s[8][4];

    // S = Q @ K^T for tile kt (32 mma)
    auto computeS = [&](int kt) {
        const uint32_t kbase = sb + (kt % NSTG) * STAGEB + lmo;
#pragma unroll
        for (int n = 0; n < 8; n++) {
#pragma unroll
            for (int q = 0; q < 4; q++) s[n][q] = 0.f;
            unsigned kb[8];
            uint32_t ka = kbase + (uint32_t)(n * 8 * ROWB);
            LDSM4(kb[0], kb[1], kb[2], kb[3], ka);
            LDSM4(kb[4], kb[5], kb[6], kb[7], ka + 64);
#pragma unroll
            for (int kc = 0; kc < 4; kc++)
                mma16(s[n], aq[kc], kb[2 * kc], kb[2 * kc + 1]);
        }
    };
    // P = exp2(S) into A-fragment registers
    auto computeP = [&](unsigned ap[4][4]) {
#pragma unroll
        for (int kc = 0; kc < 4; kc++) {
            EX2H2(ap[kc][0], s[2*kc][1],   s[2*kc][0]);
            EX2H2(ap[kc][1], s[2*kc][3],   s[2*kc][2]);
            EX2H2(ap[kc][2], s[2*kc+1][1], s[2*kc+1][0]);
            EX2H2(ap[kc][3], s[2*kc+1][3], s[2*kc+1][2]);
        }
    };
    // O += P @ V^T for tile kt (32 mma)
    auto computePV = [&](int kt, const unsigned ap[4][4]) {
        const uint32_t vbase = sb + VOFFB + (kt % NSTG) * STAGEB + lmo;
#pragma unroll
        for (int n = 0; n < 8; n++) {
            unsigned vb[8];
            uint32_t va = vbase + (uint32_t)(n * 8 * ROWB);
            LDSM4(vb[0], vb[1], vb[2], vb[3], va);
            LDSM4(vb[4], vb[5], vb[6], vb[7], va + 64);
#pragma unroll
            for (int kc = 0; kc < 4; kc++)
                mma16(oacc[n], ap[kc], vb[2 * kc], vb[2 * kc + 1]);
        }
    };
    // row-sum of P on the FMA pipe: ap[kc][0],[2] are row r0; [1],[3] row r0+8
    auto rowsum = [&](const unsigned ap[4][4]) {
        const __half2* a = (const __half2*)ap;   // a[kc*4 + q]
        __half2 h0 = __hadd2(__hadd2(a[0], a[2]),  __hadd2(a[4], a[6]));
        h0 = __hadd2(h0, __hadd2(__hadd2(a[8], a[10]), __hadd2(a[12], a[14])));
        __half2 h1 = __hadd2(__hadd2(a[1], a[3]),  __hadd2(a[5], a[7]));
        h1 = __hadd2(h1, __hadd2(__hadd2(a[9], a[11]), __hadd2(a[13], a[15])));
        float2 f0 = __half22float2(h0);
        float2 f1 = __half22float2(h1);
        l0 += f0.x + f0.y;
        l1 += f1.x + f1.y;
    };

    for (int j = 0; j < NT / 2; j++) {
        const int A = 2 * j, B = 2 * j + 1;
        if (j == NT / 2 - 1) { CPWAIT0(); } else { CPWAIT2(); }
        __syncthreads();
        if (A + 4 < NT) { issue_kv(A + 4); CPCOMMIT(); }
        if (B + 4 < NT) { issue_kv(B + 4); CPCOMMIT(); }

        unsigned apA[4][4], apB[4][4];
        computeS(A);
        computeP(apA);          // MUFU for A ...
        computeS(B);            // ... hidden under S(B) mma stream
        computePV(A, apA);
        rowsum(apA);            // FMA pipe, overlaps PV mma
        computeP(apB);
        computePV(B, apB);
        rowsum(apB);
    }

    l0 += __shfl_xor_sync(0xffffffffu, l0, 1);
    l0 += __shfl_xor_sync(0xffffffffu, l0, 2);
    l1 += __shfl_xor_sync(0xffffffffu, l1, 1);
    l1 += __shfl_xor_sync(0xffffffffu, l1, 2);
    float inv0 = 1.f / l0, inv1 = 1.f / l1;

    int srow0 = qt * 128 + r0;
#pragma unroll
    for (int n = 0; n < 8; n++) {
        int d = h * HDD + n * 8 + 2 * t;
        __half* p0 = g_ctxh + ((size_t)b_ * SS + srow0) * HH + d;
        *(unsigned*)p0 = packh2(oacc[n][0] * inv0, oacc[n][1] * inv0);
        __half* p1 = g_ctxh + ((size_t)b_ * SS + srow0 + 8) * HH + d;
        *(unsigned*)p1 = packh2(oacc[n][2] * inv1, oacc[n][3] * inv1);
    }
}

extern "C" void kernel_launch(void* const* d_in, const int* in_sizes, int n_in,
                              void* d_out, int out_size)
{
    const float* x  = (const float*)d_in[0];
    const float* Wq = (const float*)d_in[1];
    const float* bq = (const float*)d_in[2];
    const float* Wk = (const float*)d_in[3];
    const float* bk = (const float*)d_in[4];
    const float* Wv = (const float*)d_in[5];
    const float* bv = (const float*)d_in[6];
    const float* Wo = (const float*)d_in[7];
    const float* bo = (const float*)d_in[8];
    float* out = (float*)d_out;

    cudaFuncSetAttribute(flash_kernel,
                         cudaFuncAttributeMaxDynamicSharedMemorySize,
                         FLASH_SMEM);

    cvt_kernel<<<dim3(256, 5), 256>>>(x, Wq, Wk, Wv, Wo);
    qkv_kernel<<<dim3(4, 64, 3), 256>>>(bq, bk, bv);
    flash_kernel<<<dim3(SS / 128, NHH, Bb), 256, FLASH_SMEM>>>();
    proj_kernel<<<dim3(4, 64), 256>>>(bo, out);
}

// round 11
// speedup vs baseline: 1.1288x; 1.1288x over previous
#include <cuda_runtime.h>
#include <cuda_fp16.h>
#include <math.h>
#include <stdint.h>

#define Bb   2
#define SS   4096
#define HH   512
#define NHH  8
#define HDD  64
#define MTOT (Bb*SS)

#define QPREMUL (0.125f * 1.44269504088896340736f)

__device__ __half g_Xh [(size_t)MTOT*HH];
__device__ __half g_Wqh[(size_t)HH*HH];
__device__ __half g_Wkh[(size_t)HH*HH];
__device__ __half g_Wvh[(size_t)HH*HH];
__device__ __half g_Woh[(size_t)HH*HH];
__device__ __half g_Q  [(size_t)Bb*NHH*SS*HDD];   // [b,h,s,d] * scale*log2e
__device__ __half g_K  [(size_t)Bb*NHH*SS*HDD];   // [b,h,s,d]
__device__ __half g_V  [(size_t)Bb*NHH*SS*HDD];   // [b,h,d,s]  (transposed)
__device__ __half g_ctxh[(size_t)Bb*SS*HH];       // [b,s,h]

__device__ __forceinline__ unsigned packh2(float a, float b) {
    __half2 h = __floats2half2_rn(a, b);
    return *(unsigned*)&h;
}
__device__ __forceinline__ uint32_t smem_u32(const void* p) {
    return (uint32_t)__cvta_generic_to_shared(p);
}
__device__ __forceinline__ void mma16(float d[4], const unsigned a[4],
                                      unsigned b0, unsigned b1) {
    asm volatile(
        "mma.sync.aligned.m16n8k16.row.col.f32.f16.f16.f32 "
        "{%0,%1,%2,%3}, {%4,%5,%6,%7}, {%8,%9}, {%0,%1,%2,%3};"
        : "+f"(d[0]), "+f"(d[1]), "+f"(d[2]), "+f"(d[3])
        : "r"(a[0]), "r"(a[1]), "r"(a[2]), "r"(a[3]), "r"(b0), "r"(b1));
}
#define LDSM4(r0, r1, r2, r3, addr) \
    asm volatile("ldmatrix.sync.aligned.m8n8.x4.shared.b16 {%0,%1,%2,%3}, [%4];" \
        : "=r"(r0), "=r"(r1), "=r"(r2), "=r"(r3) : "r"(addr))
// half2 = {lo = exp2(slo), hi = exp2(shi)}
#define EX2H2(dst, shi, slo) do { \
    unsigned _h; \
    asm("cvt.rn.f16x2.f32 %0, %1, %2;" : "=r"(_h) : "f"(shi), "f"(slo)); \
    asm("ex2.approx.f16x2 %0, %1;" : "=r"(dst) : "r"(_h)); \
} while (0)

#define CPASYNC16(dst_u32, src_ptr) \
    asm volatile("cp.async.ca.shared.global [%0], [%1], 16;" \
                 :: "r"(dst_u32), "l"(src_ptr) : "memory")
#define CPCOMMIT()  asm volatile("cp.async.commit_group;" ::: "memory")
#define CPWAIT1()   asm volatile("cp.async.wait_group 1;" ::: "memory")
#define CPWAIT0()   asm volatile("cp.async.wait_group 0;" ::: "memory")

__global__ void __launch_bounds__(256)
cvt_kernel(const float* __restrict__ x,
           const float* __restrict__ wq, const float* __restrict__ wk,
           const float* __restrict__ wv, const float* __restrict__ wo)
{
    int seg = blockIdx.y;
    const float* src; __half* dst; int n4;
    if      (seg == 0) { src = x;  dst = g_Xh;  n4 = (MTOT * HH) / 4; }
    else if (seg == 1) { src = wq; dst = g_Wqh; n4 = (HH * HH) / 4; }
    else if (seg == 2) { src = wk; dst = g_Wkh; n4 = (HH * HH) / 4; }
    else if (seg == 3) { src = wv; dst = g_Wvh; n4 = (HH * HH) / 4; }
    else               { src = wo; dst = g_Woh; n4 = (HH * HH) / 4; }
    int stride = gridDim.x * 256;
    for (int i = blockIdx.x * 256 + threadIdx.x; i < n4; i += stride) {
        float4 v = ((const float4*)src)[i];
        ((uint2*)dst)[i] = make_uint2(packh2(v.x, v.y), packh2(v.z, v.w));
    }
}

// ---------------------------------------------------------------------------
// half GEMM, 3-stage cp.async ring (wait_group 1: compute overlaps loads),
// ldmatrix fragment loads, 2 CTAs/SM, dynamic smem.
// mode: 0 = [M,H] f32 out; 1 = g_Q half(v*premul); 2 = g_V transposed; 3 = g_K
// ---------------------------------------------------------------------------
#define GKS   20
#define GTILE (128 * GKS)                 // words per tile
#define GSMEM (6 * GTILE * 4)             // 3 X stages + 3 W stages = 61440 B

__device__ __forceinline__ void gemm128h(
    const __half* __restrict__ x, const __half* __restrict__ w,
    const float* __restrict__ bias, float* __restrict__ out,
    int bm0, int bn0, int mode, float premul)
{
    extern __shared__ unsigned gsm[];
    unsigned* Xs = gsm;                   // [3][GTILE]
    unsigned* Ws = gsm + 3 * GTILE;       // [3][GTILE]
    const uint32_t sbX = smem_u32(Xs), sbW = smem_u32(Ws);

    const int tid  = threadIdx.x;
    const int wrp  = tid >> 5;
    const int lane = tid & 31;
    const int g    = lane >> 2;
    const int t    = lane & 3;
    const int wm   = wrp >> 2;
    const int wn   = wrp & 3;

    const uint32_t lmo_b = (((uint32_t)(lane & 7)) * GKS + ((uint32_t)(lane >> 3)) * 4) * 4;
    const uint32_t lmo_a = ((((uint32_t)(lane >> 4)) * 8 + (lane & 7)) * GKS
                            + (((uint32_t)(lane >> 3)) & 1) * 4) * 4;

    auto issue_g = [&](int s) {
        int k0 = s * 32, st = s % 3;
#pragma unroll
        for (int p = 0; p < 2; p++) {
            int idx = tid + p * 256;
            int row = idx >> 2;
            int cc  = idx & 3;
            CPASYNC16(sbX + (st * GTILE + row * GKS) * 4 + cc * 16,
                      x + (size_t)(bm0 + row) * HH + k0 + cc * 8);
            CPASYNC16(sbW + (st * GTILE + row * GKS) * 4 + cc * 16,
                      w + (size_t)(bn0 + row) * HH + k0 + cc * 8);
        }
    };

    float acc[4][4][4];
#pragma unroll
    for (int i = 0; i < 4; i++)
#pragma unroll
        for (int j = 0; j < 4; j++)
#pragma unroll
            for (int q = 0; q < 4; q++) acc[i][j][q] = 0.f;

    issue_g(0); CPCOMMIT();
    issue_g(1); CPCOMMIT();

    for (int s = 0; s < 16; s++) {
        if (s == 15) { CPWAIT0(); } else { CPWAIT1(); }   // stage s complete
        __syncthreads();
        if (s + 2 < 16) { issue_g(s + 2); CPCOMMIT(); }
        const uint32_t xb = sbX + (s % 3) * GTILE * 4;
        const uint32_t wb = sbW + (s % 3) * GTILE * 4;

        unsigned bw[4][4];
#pragma unroll
        for (int j = 0; j < 4; j++)
            LDSM4(bw[j][0], bw[j][1], bw[j][2], bw[j][3],
                  wb + (uint32_t)((wn * 32 + j * 8) * GKS) * 4 + lmo_b);

#pragma unroll
        for (int kc = 0; kc < 2; kc++) {
#pragma unroll
            for (int i = 0; i < 4; i++) {
                unsigned a[4];
                LDSM4(a[0], a[2], a[1], a[3],
                      xb + (uint32_t)((wm * 64 + i * 16) * GKS + kc * 8) * 4 + lmo_a);
#pragma unroll
                for (int j = 0; j < 4; j++)
                    mma16(acc[i][j], a, bw[j][2 * kc], bw[j][2 * kc + 1]);
            }
        }
    }

#pragma unroll
    for (int i = 0; i < 4; i++) {
        int m0 = bm0 + wm * 64 + i * 16 + g;
#pragma unroll
        for (int j = 0; j < 4; j++) {
            int n = bn0 + wn * 32 + j * 8 + 2 * t;
            float bi0 = bias[n], bi1 = bias[n + 1];
#pragma unroll
            for (int rr = 0; rr < 2; rr++) {
                int m = m0 + rr * 8;
                float v0 = acc[i][j][rr * 2 + 0] + bi0;
                float v1 = acc[i][j][rr * 2 + 1] + bi1;
                if (mode == 1 || mode == 3) {
                    int b_ = m >> 12, sq = m & (SS - 1);
                    int h  = n >> 6,  d = n & 63;
                    __half* dst = (mode == 1) ? g_Q : g_K;
                    __half* p = dst + (((size_t)b_ * NHH + h) * SS + sq) * HDD + d;
                    *(unsigned*)p = packh2(v0 * premul, v1 * premul);
                } else if (mode == 2) {
                    int b_ = m >> 12, sq = m & (SS - 1);
                    int h  = n >> 6,  d = n & 63;
                    __half* base = g_V + ((size_t)b_ * NHH + h) * (size_t)HDD * SS + sq;
                    base[(size_t)d * SS]       = __float2half_rn(v0);
                    base[(size_t)(d + 1) * SS] = __float2half_rn(v1);
                } else {
                    float* p = out + (size_t)m * HH + n;
                    p[0] = v0; p[1] = v1;
                }
            }
        }
    }
}

__global__ void __launch_bounds__(256, 2)
qkv_kernel(const float* __restrict__ bq, const float* __restrict__ bk,
           const float* __restrict__ bv)
{
    int z = blockIdx.z;
    const __half* W   = (z == 0) ? g_Wqh : (z == 1) ? g_Wkh : g_Wvh;
    const float* bias = (z == 0) ? bq : (z == 1) ? bk : bv;
    int   mode        = (z == 0) ? 1 : (z == 1) ? 3 : 2;
    float premul      = (z == 0) ? QPREMUL : 1.0f;
    gemm128h(g_Xh, W, bias, nullptr, blockIdx.y * 128, blockIdx.x * 128, mode, premul);
}

__global__ void __launch_bounds__(256, 2)
proj_kernel(const float* __restrict__ bo, float* __restrict__ out)
{
    gemm128h(g_ctxh, g_Woh, bo, out, blockIdx.y * 128, blockIdx.x * 128, 0, 1.0f);
}

// ---------------------------------------------------------------------------
// Flash attention (R6 skeleton): fp16 mma + ldmatrix, 2-stage cp.async ring,
// one wait+sync per 64-key tile; f16x2 exp2; HADD2 row-sum on the FMA pipe.
// ---------------------------------------------------------------------------
#define FSTR    36
#define ROWB    144
#define STAGEB  (64 * ROWB)                 // 9216 per stage
#define NT (SS / 64)

__global__ void __launch_bounds__(256, 2)
flash_kernel()
{
    __shared__ unsigned sm[STAGEB];         // 4 stages x 9216 B (K0,K1,V0,V1)
    const uint32_t sb = smem_u32(sm);

    const int tid  = threadIdx.x;
    const int wrp  = tid >> 5;
    const int lane = tid & 31;
    const int g    = lane >> 2;
    const int t    = lane & 3;
    const int qt   = blockIdx.x;
    const int h    = blockIdx.y;
    const int b_   = blockIdx.z;

    const size_t hb = (size_t)(b_ * NHH + h);
    const __half* Qg = g_Q + hb * SS * HDD + (size_t)qt * 128 * HDD;
    const __half* Kg = g_K + hb * SS * HDD;
    const __half* Vt = g_V + hb * (size_t)HDD * SS;

    const uint32_t lmo = (((uint32_t)(lane & 7)) * FSTR + ((uint32_t)(lane >> 3)) * 4) * 4;

    auto issue_kv = [&](int kt) {
        int st = kt & 1;
#pragma unroll
        for (int p = 0; p < 2; p++) {
            int idx = tid + p * 256;
            int row = idx >> 3;
            int cc  = idx & 7;
            CPASYNC16(sb + st * STAGEB + row * ROWB + cc * 16,
                      Kg + (size_t)(kt * 64 + row) * HDD + cc * 8);
            CPASYNC16(sb + 2 * STAGEB + st * STAGEB + row * ROWB + cc * 16,
                      Vt + (size_t)row * SS + kt * 64 + cc * 8);
        }
    };

    issue_kv(0);
    CPCOMMIT();

    // Q fragments straight from gmem
    const int r0 = wrp * 16 + g;
    unsigned aq[4][4];
#pragma unroll
    for (int kc = 0; kc < 4; kc++) {
        const __half* q0 = Qg + (size_t)r0 * HDD + kc * 16 + 2 * t;
        const __half* q1 = q0 + 8 * HDD;
        aq[kc][0] = *(const unsigned*)(q0);
        aq[kc][1] = *(const unsigned*)(q1);
        aq[kc][2] = *(const unsigned*)(q0 + 8);
        aq[kc][3] = *(const unsigned*)(q1 + 8);
    }

    float oacc[8][4];
#pragma unroll
    for (int n = 0; n < 8; n++)
#pragma unroll
        for (int q = 0; q < 4; q++) oacc[n][q] = 0.f;
    float l0 = 0.f, l1 = 0.f;

    for (int kt = 0; kt < NT; kt++) {
        CPWAIT0();
        __syncthreads();
        if (kt + 1 < NT) { issue_kv(kt + 1); CPCOMMIT(); }

        const uint32_t kbase = sb + (kt & 1) * STAGEB + lmo;
        const uint32_t vbase = sb + 2 * STAGEB + (kt & 1) * STAGEB + lmo;

        // ---- S = Q @ K^T  (log2 domain) ----
        float s[8][4];
#pragma unroll
        for (int n = 0; n < 8; n++) {
#pragma unroll
            for (int q = 0; q < 4; q++) s[n][q] = 0.f;
            unsigned kb[8];
            uint32_t ka = kbase + (uint32_t)(n * 8 * ROWB);
            LDSM4(kb[0], kb[1], kb[2], kb[3], ka);
            LDSM4(kb[4], kb[5], kb[6], kb[7], ka + 64);
#pragma unroll
            for (int kc = 0; kc < 4; kc++)
                mma16(s[n], aq[kc], kb[2 * kc], kb[2 * kc + 1]);
        }

        // ---- P = exp2(S): f16x2 MUFU ----
        unsigned ap[4][4];
#pragma unroll
        for (int kc = 0; kc < 4; kc++) {
            EX2H2(ap[kc][0], s[2*kc][1],   s[2*kc][0]);
            EX2H2(ap[kc][1], s[2*kc][3],   s[2*kc][2]);
            EX2H2(ap[kc][2], s[2*kc+1][1], s[2*kc+1][0]);
            EX2H2(ap[kc][3], s[2*kc+1][3], s[2*kc+1][2]);
        }

        // ---- row-sum of P on the FMA pipe (overlaps PV mma below) ----
        {
            const __half2* a = (const __half2*)ap;   // a[kc*4 + q]
            __half2 h0 = __hadd2(__hadd2(a[0], a[2]),  __hadd2(a[4], a[6]));
            h0 = __hadd2(h0, __hadd2(__hadd2(a[8], a[10]), __hadd2(a[12], a[14])));
            __half2 h1 = __hadd2(__hadd2(a[1], a[3]),  __hadd2(a[5], a[7]));
            h1 = __hadd2(h1, __hadd2(__hadd2(a[9], a[11]), __hadd2(a[13], a[15])));
            float2 f0 = __half22float2(h0);
            float2 f1 = __half22float2(h1);
            l0 += f0.x + f0.y;
            l1 += f1.x + f1.y;
        }

        // ---- O += P @ V ----
#pragma unroll
        for (int n = 0; n < 8; n++) {
            unsigned vb[8];
            uint32_t va = vbase + (uint32_t)(n * 8 * ROWB);
            LDSM4(vb[0], vb[1], vb[2], vb[3], va);
            LDSM4(vb[4], vb[5], vb[6], vb[7], va + 64);
#pragma unroll
            for (int kc = 0; kc < 4; kc++)
                mma16(oacc[n], ap[kc], vb[2 * kc], vb[2 * kc + 1]);
        }
    }

    l0 += __shfl_xor_sync(0xffffffffu, l0, 1);
    l0 += __shfl_xor_sync(0xffffffffu, l0, 2);
    l1 += __shfl_xor_sync(0xffffffffu, l1, 1);
    l1 += __shfl_xor_sync(0xffffffffu, l1, 2);
    float inv0 = 1.f / l0, inv1 = 1.f / l1;

    int srow0 = qt * 128 + r0;
#pragma unroll
    for (int n = 0; n < 8; n++) {
        int d = h * HDD + n * 8 + 2 * t;
        __half* p0 = g_ctxh + ((size_t)b_ * SS + srow0) * HH + d;
        *(unsigned*)p0 = packh2(oacc[n][0] * inv0, oacc[n][1] * inv0);
        __half* p1 = g_ctxh + ((size_t)b_ * SS + srow0 + 8) * HH + d;
        *(unsigned*)p1 = packh2(oacc[n][2] * inv1, oacc[n][3] * inv1);
    }
}

extern "C" void kernel_launch(void* const* d_in, const int* in_sizes, int n_in,
                              void* d_out, int out_size)
{
    const float* x  = (const float*)d_in[0];
    const float* Wq = (const float*)d_in[1];
    const float* bq = (const float*)d_in[2];
    const float* Wk = (const float*)d_in[3];
    const float* bk = (const float*)d_in[4];
    const float* Wv = (const float*)d_in[5];
    const float* bv = (const float*)d_in[6];
    const float* Wo = (const float*)d_in[7];
    const float* bo = (const float*)d_in[8];
    float* out = (float*)d_out;

    cudaFuncSetAttribute(qkv_kernel,
                         cudaFuncAttributeMaxDynamicSharedMemorySize, GSMEM);
    cudaFuncSetAttribute(proj_kernel,
                         cudaFuncAttributeMaxDynamicSharedMemorySize, GSMEM);

    cvt_kernel<<<dim3(256, 5), 256>>>(x, Wq, Wk, Wv, Wo);
    qkv_kernel<<<dim3(4, 64, 3), 256, GSMEM>>>(bq, bk, bv);
    flash_kernel<<<dim3(SS / 128, NHH, Bb), 256>>>();
    proj_kernel<<<dim3(4, 64), 256, GSMEM>>>(bo, out);
}